// round 5
// baseline (speedup 1.0000x reference)
#include <cuda_runtime.h>
#include <math.h>

// Dims
#define B_ 128
#define T_ 1024
#define I_ 256
#define H_ 512
#define O_ 256

typedef unsigned long long u64;
typedef ulonglong2 u64x2;

// Device scratch (static allocations are allowed)
__device__ __align__(16) float gW1t[768 * 512];   // [k][n] k:0..511 = h-k (Whh0), 512..767 = x-k (Wih0)
__device__ __align__(16) float gW2t[512 * 512];   // [k][n]  (Wih1+Whh1, transposed)
__device__ __align__(16) float gW3t[512 * 256];   // [k][o]  (Wout transposed)
__device__ __align__(16) float g_h1[B_ * H_];
__device__ __align__(16) float g_h2[B_ * H_];

// ---------- f32x2 helpers ----------
__device__ __forceinline__ u64 pack2(float x, float y) {
    u64 r; asm("mov.b64 %0,{%1,%2};" : "=l"(r) : "f"(x), "f"(y)); return r;
}
__device__ __forceinline__ void unpack2(u64 p, float& x, float& y) {
    asm("mov.b64 {%0,%1},%2;" : "=f"(x), "=f"(y) : "l"(p));
}
__device__ __forceinline__ u64 fma2_(u64 a, u64 b, u64 c) {
    u64 d; asm("fma.rn.f32x2 %0,%1,%2,%3;" : "=l"(d) : "l"(a), "l"(b), "l"(c)); return d;
}
__device__ __forceinline__ u64 add2_(u64 a, u64 b) {
    u64 d; asm("add.rn.f32x2 %0,%1,%2;" : "=l"(d) : "l"(a), "l"(b)); return d;
}
__device__ __forceinline__ float mytanh(float x) {
    float xc = fminf(12.f, fmaxf(-12.f, x));
    float e = __expf(2.f * xc);
    return __fdividef(e - 1.f, e + 1.f);
}
__device__ __forceinline__ void cluster_bar() {
    asm volatile("barrier.cluster.arrive.aligned;" ::: "memory");
    asm volatile("barrier.cluster.wait.aligned;" ::: "memory");
}

// ---------- SMEM layout (float offsets) ----------
// W2S  : [0, 32768)           512 x 64  Wc slice, k-major
// AS   : [32768, 45184)       u64[8][776]  activation staging, DUPLICATED pairs: AS[m][k] = (v,v)
// SCR  : [45184, 49280)       u64[2048]    A/B split-K scratch
// SCRC : [49280, 51328)       u64[1024]    C split-K scratch
// b0s  : [51328, 51392)  bcs : [51392, 51456)  bos : [51456, 51488)
#define W2S_OFF  0
#define AS_OFF   32768
#define SCR_OFF  45184
#define SCRC_OFF 49280
#define B0_OFF   51328
#define BC_OFF   51392
#define BO_OFF   51456
#define SMEM_FLOATS 51488
#define SMEM_BYTES (SMEM_FLOATS * 4)
#define AS_STRIDE 776   // u64 per m row (768 k + pad)

// ---------- prep kernel: transpose / combine weights ----------
__global__ void rnn_prep(const float* __restrict__ Wih0, const float* __restrict__ Whh0,
                         const float* __restrict__ Wih1, const float* __restrict__ Whh1,
                         const float* __restrict__ Wout) {
    int i = blockIdx.x * blockDim.x + threadIdx.x;
    if (i < 768 * 512) {
        int k = i >> 9, n = i & 511;
        gW1t[i] = (k < 512) ? Whh0[n * 512 + k] : Wih0[n * 256 + (k - 512)];
    }
    if (i < 512 * 512) {
        int k = i >> 9, n = i & 511;
        gW2t[i] = Wih1[n * 512 + k] + Whh1[n * 512 + k];
    }
    if (i < 512 * 256) {
        int k = i >> 8, o = i & 255;
        gW3t[i] = Wout[o * 512 + k];
    }
}

// ---------- staging: global h (8 rows x 512) -> AS duplicated ----------
__device__ __forceinline__ void stage_h(u64* AS, const float* src, int grp8, int tid) {
    int m = tid >> 6, cu = tid & 63;
    const u64* row = reinterpret_cast<const u64*>(src + (size_t)(grp8 + m) * 512);
    u64* dst = AS + m * AS_STRIDE;
#pragma unroll
    for (int i = 0; i < 4; i++) {
        int w = cu + 64 * i;                 // u64 word index (coalesced per instr)
        u64 v = __ldcg(row + w);
        float v0, v1; unpack2(v, v0, v1);
        dst[2 * w]     = pack2(v0, v0);
        dst[2 * w + 1] = pack2(v1, v1);
    }
}
__device__ __forceinline__ void stage_x(u64* AS, const float* x, int grp8, int t, int tid) {
    int m = tid >> 6, cu = tid & 63;
    const u64* row = reinterpret_cast<const u64*>(x + ((size_t)(grp8 + m) * T_ + t) * I_);
    u64* dst = AS + m * AS_STRIDE + 512;
#pragma unroll
    for (int i = 0; i < 2; i++) {
        int w = cu + 64 * i;
        u64 v = __ldg(row + w);
        float v0, v1; unpack2(v, v0, v1);
        dst[2 * w]     = pack2(v0, v0);
        dst[2 * w + 1] = pack2(v1, v1);
    }
}

// ---------- main persistent kernel ----------
__global__ void __launch_bounds__(512, 1) __cluster_dims__(8, 1, 1)
rnn_main(const float* __restrict__ x, const float* __restrict__ h0,
         const float* __restrict__ bih0, const float* __restrict__ bhh0,
         const float* __restrict__ bih1, const float* __restrict__ bhh1,
         const float* __restrict__ bout, float* __restrict__ out) {
    extern __shared__ float smem[];
    float* W2S = smem + W2S_OFF;
    u64*   AS   = reinterpret_cast<u64*>(smem + AS_OFF);
    u64*   SCR  = reinterpret_cast<u64*>(smem + SCR_OFF);
    u64*   SCRC = reinterpret_cast<u64*>(smem + SCRC_OFF);
    float* b0s = smem + B0_OFF;
    float* bcs = smem + BC_OFF;
    float* bos = smem + BO_OFF;

    const int tid  = threadIdx.x;
    const int grp  = blockIdx.x >> 3;     // 16 batch groups
    const int rank = blockIdx.x & 7;      // column slice within cluster
    const int grp8 = grp * 8;
    const int nb = rank * 64;             // hidden col base
    const int ob = rank * 32;             // output col base

    const int ks = tid >> 6;              // split-K part 0..7
    const int m8 = (tid >> 3) & 7;        // batch row within group
    const int cg = tid & 7;               // col-group (8 cols for A/B, 4 for C)

    // ---- resident weight slice + biases ----
    for (int i = tid; i < 512 * 64; i += 512) {
        int k = i >> 6, j = i & 63;
        W2S[i] = gW2t[k * 512 + nb + j];
    }
    if (tid < 64) b0s[tid] = bih0[nb + tid] + bhh0[nb + tid];
    if (tid < 64) bcs[tid] = bih1[nb + tid] + bhh1[nb + tid];
    if (tid < 32) bos[tid] = bout[ob + tid];

    stage_h(AS, h0, grp8, tid);
    stage_x(AS, x, grp8, 0, tid);
    __syncthreads();

    const float* W1base = gW1t + nb + cg * 8;
    const float* W3base = gW3t + ob + cg * 4;
    const u64*   actA   = AS + m8 * AS_STRIDE;

    for (int t = 0; t < T_; t++) {
        // ================= Phase A: h1 = tanh([h;x] @ W1^T + b0) =================
        u64 a0 = 0, a1 = 0, a2 = 0, a3 = 0;
        {
            const float* wp = W1base + (size_t)(ks * 96) * 512;
            const u64*   ap = actA + ks * 96;
#pragma unroll 1
            for (int blk = 0; blk < 12; blk++) {
                u64x2 w[8][2];
#pragma unroll
                for (int i = 0; i < 8; i++) {
                    w[i][0] = *reinterpret_cast<const u64x2*>(wp + (size_t)i * 512);
                    w[i][1] = *reinterpret_cast<const u64x2*>(wp + (size_t)i * 512 + 4);
                }
#pragma unroll
                for (int i = 0; i < 8; i++) {
                    u64 a = ap[i];
                    a0 = fma2_(a, w[i][0].x, a0);
                    a1 = fma2_(a, w[i][0].y, a1);
                    a2 = fma2_(a, w[i][1].x, a2);
                    a3 = fma2_(a, w[i][1].y, a3);
                }
                wp += 8 * 512; ap += 8;
            }
        }
        __syncthreads();
        SCR[tid * 4 + 0] = a0; SCR[tid * 4 + 1] = a1;
        SCR[tid * 4 + 2] = a2; SCR[tid * 4 + 3] = a3;
        __syncthreads();
        if (tid < 256) {
            int m = tid >> 5, cp = tid & 31;
            u64 s = SCR[m * 32 + cp];
#pragma unroll
            for (int k2 = 1; k2 < 8; k2++) s = add2_(s, SCR[k2 * 256 + m * 32 + cp]);
            int col = ((cp >> 2) << 3) + ((cp & 3) << 1);
            s = add2_(s, *reinterpret_cast<const u64*>(b0s + col));
            float v0, v1; unpack2(s, v0, v1);
            v0 = mytanh(v0); v1 = mytanh(v1);
            *reinterpret_cast<u64*>(&g_h1[(grp8 + m) * 512 + nb + col]) = pack2(v0, v1);
            __threadfence();
        }
        cluster_bar();  // exchange h1

        stage_h(AS, g_h1, grp8, tid);
        __syncthreads();

        // ================= Phase B: h2 = tanh(h1 @ Wc^T + bc) =================
        a0 = 0; a1 = 0; a2 = 0; a3 = 0;
        {
            const float* wp = W2S + (ks * 64) * 64 + cg * 8;
            const u64*   ap = actA + ks * 64;
#pragma unroll 8
            for (int i = 0; i < 64; i++) {
                u64x2 w0 = *reinterpret_cast<const u64x2*>(wp + i * 64);
                u64x2 w1 = *reinterpret_cast<const u64x2*>(wp + i * 64 + 4);
                u64 a = ap[i];
                a0 = fma2_(a, w0.x, a0);
                a1 = fma2_(a, w0.y, a1);
                a2 = fma2_(a, w1.x, a2);
                a3 = fma2_(a, w1.y, a3);
            }
        }
        __syncthreads();
        SCR[tid * 4 + 0] = a0; SCR[tid * 4 + 1] = a1;
        SCR[tid * 4 + 2] = a2; SCR[tid * 4 + 3] = a3;
        __syncthreads();
        if (tid < 256) {
            int m = tid >> 5, cp = tid & 31;
            u64 s = SCR[m * 32 + cp];
#pragma unroll
            for (int k2 = 1; k2 < 8; k2++) s = add2_(s, SCR[k2 * 256 + m * 32 + cp]);
            int col = ((cp >> 2) << 3) + ((cp & 3) << 1);
            s = add2_(s, *reinterpret_cast<const u64*>(bcs + col));
            float v0, v1; unpack2(s, v0, v1);
            v0 = mytanh(v0); v1 = mytanh(v1);
            *reinterpret_cast<u64*>(&g_h2[(grp8 + m) * 512 + nb + col]) = pack2(v0, v1);
            __threadfence();
        }
        cluster_bar();  // exchange h2 (feeds phase C and next step's phase A)

        stage_h(AS, g_h2, grp8, tid);
        int tn = (t + 1 < T_) ? (t + 1) : t;
        stage_x(AS, x, grp8, tn, tid);
        __syncthreads();

        // ================= Phase C: y = h2 @ Wout^T + b_out =================
        u64 c0 = 0, c1 = 0;
        {
            const float* wp = W3base + (size_t)(ks * 64) * 256;
            const u64*   ap = actA + ks * 64;
#pragma unroll 1
            for (int blk = 0; blk < 8; blk++) {
                u64x2 w[8];
#pragma unroll
                for (int i = 0; i < 8; i++)
                    w[i] = *reinterpret_cast<const u64x2*>(wp + (size_t)i * 256);
#pragma unroll
                for (int i = 0; i < 8; i++) {
                    u64 a = ap[i];
                    c0 = fma2_(a, w[i].x, c0);
                    c1 = fma2_(a, w[i].y, c1);
                }
                wp += 8 * 256; ap += 8;
            }
        }
        __syncthreads();
        SCRC[tid * 2 + 0] = c0; SCRC[tid * 2 + 1] = c1;
        __syncthreads();
        if (tid < 128) {
            int m = tid >> 4, cp = tid & 15;
            u64 s = SCRC[m * 16 + cp];
#pragma unroll
            for (int k2 = 1; k2 < 8; k2++) s = add2_(s, SCRC[k2 * 128 + m * 16 + cp]);
            int col = ((cp >> 1) << 2) + ((cp & 1) << 1);
            s = add2_(s, *reinterpret_cast<const u64*>(bos + col));
            *reinterpret_cast<u64*>(
                &out[(size_t)(grp8 + m) * (T_ * O_) + (size_t)t * O_ + ob + col]) = s;
        }
        // no extra sync: next phase-A reads only AS (stable); SCR rewrite is
        // guarded by the sync after the next A k-loop.
    }
}

extern "C" void kernel_launch(void* const* d_in, const int* in_sizes, int n_in,
                              void* d_out, int out_size) {
    const float* x    = (const float*)d_in[0];
    const float* h0   = (const float*)d_in[1];
    const float* Wih0 = (const float*)d_in[2];
    const float* bih0 = (const float*)d_in[3];
    const float* Whh0 = (const float*)d_in[4];
    const float* bhh0 = (const float*)d_in[5];
    const float* Wih1 = (const float*)d_in[6];
    const float* bih1 = (const float*)d_in[7];
    const float* Whh1 = (const float*)d_in[8];
    const float* bhh1 = (const float*)d_in[9];
    const float* Wout = (const float*)d_in[10];
    const float* bout = (const float*)d_in[11];
    float* out = (float*)d_out;

    cudaFuncSetAttribute(rnn_main, cudaFuncAttributeMaxDynamicSharedMemorySize, SMEM_BYTES);

    rnn_prep<<<(768 * 512 + 255) / 256, 256>>>(Wih0, Whh0, Wih1, Whh1, Wout);
    rnn_main<<<128, 512, SMEM_BYTES>>>(x, h0, bih0, bhh0, bih1, bhh1, bout, out);
}